// round 11
// baseline (speedup 1.0000x reference)
#include <cuda_runtime.h>
#include <math.h>

// BPR loss:
//   per_sample[b] = -( sum_{i<L, j<L, k<S} log_sigmoid( out[b,i,lab[b,j]] - out[b,i,neg[b,j,k]] ) ) / (L^2 * S)
//   result = sum_b per_sample[b]     (shape [1], float32)
//
// Inputs (harness delivers int64 as int32):
//   d_in[0] output  : float32 [B, T, V]
//   d_in[1] labels  : int32   [B, T]
//   d_in[2] x_lens  : int32   [B]
//   d_in[3] uids    : int32   [B, 1]  (unused)
//   d_in[4] neg_ids : int32   [B, T, S]
//
// R11: persistent WARP-per-row kernel. R10 showed block-persistent loses to
// per-row __syncthreads draining the gather pipeline; here warps stride the
// (b,i) space independently -- zero barriers, zero wave quantization, dead
// rows cost ~10 instructions. Reduction: warp shfl + one atomicAdd per row.
// Gathers __ldcg (L2-only). No gpu-scope fences (R7/R8: CCTL.IVALL ~8us).

#define PERSIST_BLOCKS 1184   // 148 SMs * 8 blocks (256 thr, one resident wave)

__global__ void zero_out_kernel(float* __restrict__ out) {
    if (threadIdx.x == 0) out[0] = 0.0f;
}

__device__ __forceinline__ float warp_reduce_add(float v) {
#pragma unroll
    for (int off = 16; off > 0; off >>= 1)
        v += __shfl_down_sync(0xFFFFFFFFu, v, off);
    return v;
}

__device__ __forceinline__ float log_sigmoid_fast(float d) {
    // min(d,0) - log(1 + exp(-|d|)); exp arg <= 0 so log arg in (1,2]
    return fminf(d, 0.0f) - __logf(1.0f + __expf(-fabsf(d)));
}

__global__ void __launch_bounds__(256)
bpr_loss_kernel(const float* __restrict__ out3d,   // [B,T,V]
                const int* __restrict__ labels,    // [B,T]
                const int* __restrict__ x_lens,    // [B]
                const int* __restrict__ neg_ids,   // [B,T,S]
                float* __restrict__ result,        // [1]
                int B, int T, int V, int S)
{
    const int lane = threadIdx.x & 31;
    const int gwarp  = blockIdx.x * (blockDim.x >> 5) + (threadIdx.x >> 5);
    const int nwarps = gridDim.x * (blockDim.x >> 5);

    const int total = B * T;
    for (int f = gwarp; f < total; f += nwarps) {
        const int b = f / T;
        const int i = f - b * T;
        const int L = __ldg(x_lens + b);
        if (i >= L) continue;

        const float* __restrict__ row = out3d + (size_t)f * (size_t)V;
        const int* __restrict__ lab = labels + (size_t)b * T;
        const int* __restrict__ neg = neg_ids + (size_t)b * T * S;

        float acc = 0.0f;
        if (S == 1) {
            for (int j = lane; j < L; j += 32) {
                const int c_pos = __ldg(lab + j);
                const int c_neg = __ldg(neg + j);
                const float pv = __ldcg(row + c_pos);
                const float nv = __ldcg(row + c_neg);
                acc += log_sigmoid_fast(pv - nv);
            }
        } else {
            for (int j = lane; j < L; j += 32) {
                const float pv = __ldcg(row + __ldg(lab + j));
                for (int k = 0; k < S; ++k)
                    acc += log_sigmoid_fast(pv - __ldcg(row + __ldg(neg + (size_t)j * S + k)));
            }
        }

        acc = warp_reduce_add(acc);
        if (lane == 0) {
            const float Lf = (float)L;
            atomicAdd(result, acc * (-1.0f / (Lf * Lf * (float)S)));
        }
    }
}

extern "C" void kernel_launch(void* const* d_in, const int* in_sizes, int n_in,
                              void* d_out, int out_size)
{
    const float* out3d   = (const float*)d_in[0];
    const int*   labels  = (const int*)d_in[1];
    const int*   x_lens  = (const int*)d_in[2];
    const int*   neg_ids = (const int*)d_in[4];
    float* result = (float*)d_out;

    const int B = in_sizes[2];                 // x_lens: B
    const int T = in_sizes[1] / B;             // labels: B*T
    const int V = in_sizes[0] / (B * T);       // output: B*T*V
    const int S = in_sizes[4] / (B * T);       // neg_ids: B*T*S

    zero_out_kernel<<<1, 32>>>(result);

    bpr_loss_kernel<<<PERSIST_BLOCKS, 256>>>(out3d, labels, x_lens, neg_ids,
                                             result, B, T, V, S);
}

// round 12
// speedup vs baseline: 1.2273x; 1.2273x over previous
#include <cuda_runtime.h>
#include <math.h>

// BPR loss:
//   per_sample[b] = -( sum_{i<L, j<L, k<S} log_sigmoid( out[b,i,lab[b,j]] - out[b,i,neg[b,j,k]] ) ) / (L^2 * S)
//   result = sum_b per_sample[b]     (shape [1], float32)
//
// Inputs (harness delivers int64 as int32):
//   d_in[0] output  : float32 [B, T, V]
//   d_in[1] labels  : int32   [B, T]
//   d_in[2] x_lens  : int32   [B]
//   d_in[3] uids    : int32   [B, 1]  (unused)
//   d_in[4] neg_ids : int32   [B, T, S]
//
// FINAL (R6 config) — converged after 10 controlled experiments:
//  * block-per-row, 256 thr, grid (T,B): oversubscribed grid self-load-balances
//    (beats persistent variants: R10 barrier drain, R11 MLP-pool/tail).
//  * __ldcg row gathers (L2-only; neutral vs __ldg but avoids L1 pollution).
//  * separate 1-block zero kernel (cheaper than memset graph node, R9; and no
//    gpu-scope fence fusion — __threadfence = per-block CCTL.IVALL L1 flush,
//    cost ~8us at this grid, R7/R8).
//  * kernel is at the random-gather DRAM floor: ~5.5 TB/s, ~69% DRAM active,
//    ~177MB effective traffic for ~7MB useful data (64B+ granularity on
//    random 4B gathers). Sorting (R4/R5) and MLP batching (R3) cannot beat it.

__global__ void zero_out_kernel(float* __restrict__ out) {
    if (threadIdx.x == 0) out[0] = 0.0f;
}

__device__ __forceinline__ float warp_reduce_add(float v) {
#pragma unroll
    for (int off = 16; off > 0; off >>= 1)
        v += __shfl_down_sync(0xFFFFFFFFu, v, off);
    return v;
}

__device__ __forceinline__ float log_sigmoid_fast(float d) {
    // min(d,0) - log(1 + exp(-|d|)); exp arg <= 0 so log arg in (1,2]
    return fminf(d, 0.0f) - __logf(1.0f + __expf(-fabsf(d)));
}

__global__ void __launch_bounds__(256)
bpr_loss_kernel(const float* __restrict__ out3d,   // [B,T,V]
                const int* __restrict__ labels,    // [B,T]
                const int* __restrict__ x_lens,    // [B]
                const int* __restrict__ neg_ids,   // [B,T,S]
                float* __restrict__ result,        // [1]
                int T, int V, int S)
{
    const int b = blockIdx.y;
    const int i = blockIdx.x;
    const int L = x_lens[b];
    if (i >= L) return;

    const float* __restrict__ row = out3d + ((size_t)b * T + i) * (size_t)V;
    const int* __restrict__ lab = labels + (size_t)b * T;
    const int* __restrict__ neg = neg_ids + (size_t)b * T * S;

    float acc = 0.0f;
    if (S == 1) {
        for (int j = threadIdx.x; j < L; j += blockDim.x) {
            const int c_pos = __ldg(lab + j);
            const int c_neg = __ldg(neg + j);
            const float pv = __ldcg(row + c_pos);
            const float nv = __ldcg(row + c_neg);
            acc += log_sigmoid_fast(pv - nv);
        }
    } else {
        for (int j = threadIdx.x; j < L; j += blockDim.x) {
            const float pv = __ldcg(row + __ldg(lab + j));
            for (int k = 0; k < S; ++k)
                acc += log_sigmoid_fast(pv - __ldcg(row + __ldg(neg + (size_t)j * S + k)));
        }
    }

    // block reduction
    __shared__ float warp_sums[8];
    const int lane = threadIdx.x & 31;
    const int wid  = threadIdx.x >> 5;
    acc = warp_reduce_add(acc);
    if (lane == 0) warp_sums[wid] = acc;
    __syncthreads();
    if (wid == 0) {
        float v = (lane < 8) ? warp_sums[lane] : 0.0f;
        v = warp_reduce_add(v);
        if (lane == 0) {
            const float Lf = (float)L;
            atomicAdd(result, v * (-1.0f / (Lf * Lf * (float)S)));
        }
    }
}

extern "C" void kernel_launch(void* const* d_in, const int* in_sizes, int n_in,
                              void* d_out, int out_size)
{
    const float* out3d   = (const float*)d_in[0];
    const int*   labels  = (const int*)d_in[1];
    const int*   x_lens  = (const int*)d_in[2];
    const int*   neg_ids = (const int*)d_in[4];
    float* result = (float*)d_out;

    const int B = in_sizes[2];                 // x_lens: B
    const int T = in_sizes[1] / B;             // labels: B*T
    const int V = in_sizes[0] / (B * T);       // output: B*T*V
    const int S = in_sizes[4] / (B * T);       // neg_ids: B*T*S

    zero_out_kernel<<<1, 32>>>(result);

    dim3 grid(T, B);
    bpr_loss_kernel<<<grid, 256>>>(out3d, labels, x_lens, neg_ids, result, T, V, S);
}

// round 13
// speedup vs baseline: 1.2368x; 1.0077x over previous
#include <cuda_runtime.h>
#include <math.h>

// BPR loss:
//   per_sample[b] = -( sum_{i<L, j<L, k<S} log_sigmoid( out[b,i,lab[b,j]] - out[b,i,neg[b,j,k]] ) ) / (L^2 * S)
//   result = sum_b per_sample[b]     (shape [1], float32)
//
// Inputs (harness delivers int64 as int32):
//   d_in[0] output  : float32 [B, T, V]
//   d_in[1] labels  : int32   [B, T]
//   d_in[2] x_lens  : int32   [B]
//   d_in[3] uids    : int32   [B, 1]  (unused)
//   d_in[4] neg_ids : int32   [B, T, S]
//
// R13 = R6/R12 config with blockDim 256 -> 128. The 128-thread variable was
// confounded with the __threadfence L1-flush in R7 (R8 proved the fence alone
// costs ~8us). With avg L~100, 256-thr blocks leave warps 4-7 gather-idle;
// 128-thr blocks (16 resident/SM, same 64 warps/SM) make nearly every
// resident warp memory-active -> ~2x outstanding gathers per SM.

__global__ void zero_out_kernel(float* __restrict__ out) {
    if (threadIdx.x == 0) out[0] = 0.0f;
}

__device__ __forceinline__ float warp_reduce_add(float v) {
#pragma unroll
    for (int off = 16; off > 0; off >>= 1)
        v += __shfl_down_sync(0xFFFFFFFFu, v, off);
    return v;
}

__device__ __forceinline__ float log_sigmoid_fast(float d) {
    // min(d,0) - log(1 + exp(-|d|)); exp arg <= 0 so log arg in (1,2]
    return fminf(d, 0.0f) - __logf(1.0f + __expf(-fabsf(d)));
}

__global__ void __launch_bounds__(128)
bpr_loss_kernel(const float* __restrict__ out3d,   // [B,T,V]
                const int* __restrict__ labels,    // [B,T]
                const int* __restrict__ x_lens,    // [B]
                const int* __restrict__ neg_ids,   // [B,T,S]
                float* __restrict__ result,        // [1]
                int T, int V, int S)
{
    const int b = blockIdx.y;
    const int i = blockIdx.x;
    const int L = x_lens[b];
    if (i >= L) return;

    const float* __restrict__ row = out3d + ((size_t)b * T + i) * (size_t)V;
    const int* __restrict__ lab = labels + (size_t)b * T;
    const int* __restrict__ neg = neg_ids + (size_t)b * T * S;

    float acc = 0.0f;
    if (S == 1) {
        for (int j = threadIdx.x; j < L; j += blockDim.x) {
            const int c_pos = __ldg(lab + j);
            const int c_neg = __ldg(neg + j);
            const float pv = __ldcg(row + c_pos);
            const float nv = __ldcg(row + c_neg);
            acc += log_sigmoid_fast(pv - nv);
        }
    } else {
        for (int j = threadIdx.x; j < L; j += blockDim.x) {
            const float pv = __ldcg(row + __ldg(lab + j));
            for (int k = 0; k < S; ++k)
                acc += log_sigmoid_fast(pv - __ldcg(row + __ldg(neg + (size_t)j * S + k)));
        }
    }

    // block reduction (4 warps)
    __shared__ float warp_sums[4];
    const int lane = threadIdx.x & 31;
    const int wid  = threadIdx.x >> 5;
    acc = warp_reduce_add(acc);
    if (lane == 0) warp_sums[wid] = acc;
    __syncthreads();
    if (wid == 0) {
        float v = (lane < 4) ? warp_sums[lane] : 0.0f;
        v = warp_reduce_add(v);
        if (lane == 0) {
            const float Lf = (float)L;
            atomicAdd(result, v * (-1.0f / (Lf * Lf * (float)S)));
        }
    }
}

extern "C" void kernel_launch(void* const* d_in, const int* in_sizes, int n_in,
                              void* d_out, int out_size)
{
    const float* out3d   = (const float*)d_in[0];
    const int*   labels  = (const int*)d_in[1];
    const int*   x_lens  = (const int*)d_in[2];
    const int*   neg_ids = (const int*)d_in[4];
    float* result = (float*)d_out;

    const int B = in_sizes[2];                 // x_lens: B
    const int T = in_sizes[1] / B;             // labels: B*T
    const int V = in_sizes[0] / (B * T);       // output: B*T*V
    const int S = in_sizes[4] / (B * T);       // neg_ids: B*T*S

    zero_out_kernel<<<1, 32>>>(result);

    dim3 grid(T, B);
    bpr_loss_kernel<<<grid, 128>>>(out3d, labels, x_lens, neg_ids, result, T, V, S);
}